// round 3
// baseline (speedup 1.0000x reference)
#include <cuda_runtime.h>
#include <cuda_bf16.h>
#include <cstdint>
#include <cstddef>

// ---------------- problem constants ----------------
static constexpr int DK   = 4096;          // inner dim == output dim
static constexpr int MTOT = 4096;          // B*S
static constexpr int TM = 128, TN = 128;   // CTA tile
static constexpr int TKB = 128;            // k-bytes per stage (128 s8)
static constexpr int NMT = MTOT / TM;      // 32
static constexpr int NNT = DK / TN;        // 32
static constexpr int NKS = DK / TKB;       // 32 k-stages (single pass)
static constexpr int STAGES = 4;
static constexpr int TILE_BYTES  = 16384;                    // each of AH/AL/B
static constexpr int STAGE_BYTES = 3 * TILE_BYTES;           // 49152
static constexpr int SMEM_BYTES  = 1024 + STAGES * STAGE_BYTES; // 197632

// ---------------- scratch (pre-packed, pre-swizzled s8/u8 tiles) ------------
__device__ __align__(1024) uint8_t g_AH[(size_t)NMT * NKS * TILE_BYTES]; // 16MB
__device__ __align__(1024) uint8_t g_AL[(size_t)NMT * NKS * TILE_BYTES]; // 16MB
__device__ __align__(1024) uint8_t g_B [(size_t)NNT * NKS * TILE_BYTES]; // 16MB
__device__ float g_a[MTOT];     // per-row quant scale
__device__ int   g_irs[MTOT];   // per-row integer sum of X

// ---------------- helpers ----------------
__device__ __forceinline__ uint32_t smem_u32(const void* p) {
    uint32_t a;
    asm("{ .reg .u64 t; cvta.to.shared.u64 t, %1; cvt.u32.u64 %0, t; }"
        : "=r"(a) : "l"(p));
    return a;
}
__device__ __forceinline__ uint32_t swz(uint32_t off) {   // 128B-row swizzle
    return off ^ ((off >> 3) & 0x70);
}

#define MBAR_INIT(mbar, cnt) \
    asm volatile("mbarrier.init.shared.b64 [%0], %1;" :: "r"(mbar), "r"(cnt) : "memory")
#define MBAR_ARRIVE(mbar) \
    asm volatile("mbarrier.arrive.shared.b64 _, [%0];" :: "r"(mbar) : "memory")
#define MBAR_EXPECT_TX(mbar, bytes) \
    asm volatile("mbarrier.arrive.expect_tx.shared.b64 _, [%0], %1;" \
                 :: "r"(mbar), "r"(bytes) : "memory")
#define MBAR_WAIT(mbar, parity) do {                                          \
    asm volatile(                                                             \
        "{\n\t.reg .pred P1;\n\t"                                             \
        "W_%=:\n\t"                                                           \
        "mbarrier.try_wait.parity.acquire.cta.shared::cta.b64 P1, [%0], %1, 0x989680;\n\t" \
        "@P1 bra.uni D_%=;\n\t"                                               \
        "bra.uni W_%=;\n\t"                                                   \
        "D_%=:\n\t}"                                                          \
        :: "r"((uint32_t)(mbar)), "r"((uint32_t)(parity)) : "memory");        \
} while (0)
#define BULK_G2S(dst, src, bytes, mbar)                                       \
    asm volatile(                                                             \
        "cp.async.bulk.shared::cluster.global.mbarrier::complete_tx::bytes "  \
        "[%0], [%1], %2, [%3];"                                               \
        :: "r"((uint32_t)(dst)), "l"(src), "r"((uint32_t)(bytes)),            \
           "r"((uint32_t)(mbar)) : "memory")

#define LDSM_X4(r0, r1, r2, r3, addr)                                         \
    asm volatile("ldmatrix.sync.aligned.m8n8.x4.shared.b16 {%0,%1,%2,%3}, [%4];" \
        : "=r"(r0), "=r"(r1), "=r"(r2), "=r"(r3) : "r"(addr))

// s8 (A) x u8 (B) -> s32, K=32 per instruction
#define IMMA16832(d, a, b0, b1)                                               \
    asm volatile(                                                             \
        "mma.sync.aligned.m16n8k32.row.col.s32.s8.u8.s32 "                    \
        "{%0,%1,%2,%3}, {%4,%5,%6,%7}, {%8,%9}, {%0,%1,%2,%3};"               \
        : "+r"((d)[0]), "+r"((d)[1]), "+r"((d)[2]), "+r"((d)[3])              \
        : "r"((a)[0]), "r"((a)[1]), "r"((a)[2]), "r"((a)[3]),                 \
          "r"(b0), "r"(b1))

// ---------------- stage-0 kernels ----------------
// per-row |max| -> scale a[m]; zero the integer rowsum
__global__ void __launch_bounds__(256) rowmax_kernel(const float* __restrict__ x) {
    __shared__ float red[256];
    int r = blockIdx.x, t = threadIdx.x;
    float m = 0.0f;
#pragma unroll
    for (int j = 0; j < 16; j++) m = fmaxf(m, fabsf(x[(size_t)r * DK + t + j * 256]));
    red[t] = m;
    __syncthreads();
#pragma unroll
    for (int o = 128; o > 0; o >>= 1) {
        if (t < o) red[t] = fmaxf(red[t], red[t + o]);
        __syncthreads();
    }
    if (t == 0) {
        g_a[r] = red[0] / 32600.0f + 1e-30f;
        g_irs[r] = 0;
    }
}

// x -> two s8 digits (H,L), pre-swizzled tiles [mt][ks][128 rows x 128 kB]
__global__ void __launch_bounds__(256) pack_x_kernel(const float* __restrict__ x) {
    int b = blockIdx.x;                 // mt*32 + ks
    int mt = b >> 5, ks = b & 31;
    size_t tbase = (size_t)b * TILE_BYTES;
#pragma unroll
    for (int p = 0; p < 4; p++) {
        int u = threadIdx.x + p * 256;  // [0,1024)
        int row = u >> 3, chunk = u & 7;
        int gr = mt * 128 + row;
        const float* src = x + (size_t)gr * DK + ks * 128 + chunk * 16;
        float v[16];
#pragma unroll
        for (int i = 0; i < 4; i++) {
            float4 f = *reinterpret_cast<const float4*>(src + 4 * i);
            v[4 * i] = f.x; v[4 * i + 1] = f.y; v[4 * i + 2] = f.z; v[4 * i + 3] = f.w;
        }
        float inv = 1.0f / g_a[gr];
        uint32_t hw[4], lw[4];
        int sum = 0;
#pragma unroll
        for (int i = 0; i < 4; i++) {
            uint32_t h = 0, l = 0;
#pragma unroll
            for (int j = 0; j < 4; j++) {
                int X = __float2int_rn(v[4 * i + j] * inv);
                sum += X;
                int H = (X + 128) >> 8;
                int L = X - (H << 8);
                h |= (uint32_t)(H & 0xFF) << (8 * j);
                l |= (uint32_t)(L & 0xFF) << (8 * j);
            }
            hw[i] = h; lw[i] = l;
        }
        uint32_t off = swz((uint32_t)(row * 128 + chunk * 16));
        *reinterpret_cast<uint4*>(g_AH + tbase + off) = make_uint4(hw[0], hw[1], hw[2], hw[3]);
        *reinterpret_cast<uint4*>(g_AL + tbase + off) = make_uint4(lw[0], lw[1], lw[2], lw[3]);
        atomicAdd(&g_irs[gr], sum);
    }
}

// q[k][n] int32 (0..255) -> u8 tiles [nt][ks][128 n-rows x 128 kB], transposed
__global__ void __launch_bounds__(256) pack_q_kernel(const int* __restrict__ q) {
    int b = blockIdx.x;                 // nt*32 + ks
    int nt = b >> 5, ks = b & 31;
    size_t tbase = (size_t)b * TILE_BYTES;
#pragma unroll
    for (int p = 0; p < 4; p++) {
        int u = p * 256 + threadIdx.x;
        int nl = u & 127, chunk = u >> 7;           // chunk 0..7
        int n = nt * 128 + nl;
        int k0 = ks * 128 + chunk * 16;
        uint32_t w[4];
#pragma unroll
        for (int i = 0; i < 4; i++) {
            uint32_t ww = 0;
#pragma unroll
            for (int j = 0; j < 4; j++) {
                int vq = q[(size_t)(k0 + 4 * i + j) * DK + n];
                ww |= (uint32_t)(vq & 0xFF) << (8 * j);
            }
            w[i] = ww;
        }
        uint32_t off = swz((uint32_t)(nl * 128 + chunk * 16));
        *reinterpret_cast<uint4*>(g_B + tbase + off) = make_uint4(w[0], w[1], w[2], w[3]);
    }
}

// ---------------- main GEMM: IMMA s8xu8, 4-stage bulk-copy pipeline ---------
__global__ void __launch_bounds__(256, 1)
ffq_gemm_kernel(const float* __restrict__ scale, const int* __restrict__ zp,
                const float* __restrict__ bias, float* __restrict__ out) {
    extern __shared__ char smem_raw[];
    uint32_t sb = (smem_u32(smem_raw) + 1023u) & ~1023u;   // ctrl base
    const uint32_t data = sb + 1024;

    const int tid = threadIdx.x;
    const int wid = tid >> 5, lid = tid & 31;
    const int nt = blockIdx.x, mtb = blockIdx.y;
    const int mwarp = wid & 3;            // 4 warps over M (32 rows each)
    const int nwarp = wid >> 2;           // 2 warps over N (64 cols each)

    if (tid == 0) {
#pragma unroll
        for (int s = 0; s < STAGES; s++) {
            MBAR_INIT(sb + 8 * s, 1);        // full[s], tx-based
            MBAR_INIT(sb + 64 + 8 * s, 8);   // empty[s], 8 warp arrivals
        }
        asm volatile("fence.proxy.async.shared::cta;" ::: "memory");
    }
    __syncthreads();

    // prologue: fill stages 0..3 (ks = s)
    if (tid == 0) {
#pragma unroll
        for (int s = 0; s < STAGES; s++) {
            size_t tb = (size_t)(mtb * NKS + s) * TILE_BYTES;
            size_t bb = (size_t)(nt * NKS + s) * TILE_BYTES;
            uint32_t st = data + s * STAGE_BYTES;
            MBAR_EXPECT_TX(sb + 8 * s, STAGE_BYTES);
            BULK_G2S(st,                  g_AH + tb, TILE_BYTES, sb + 8 * s);
            BULK_G2S(st + TILE_BYTES,     g_AL + tb, TILE_BYTES, sb + 8 * s);
            BULK_G2S(st + 2 * TILE_BYTES, g_B  + bb, TILE_BYTES, sb + 8 * s);
        }
    }

    // per-lane ldmatrix address components
    const int li = lid & 7, lg = lid >> 3;
    const uint32_t xorc = (uint32_t)li << 4;
    const uint32_t a_row = (uint32_t)(mwarp * 32 + (lg & 1) * 8 + li);   // + mt*16
    const uint32_t a_colh = (uint32_t)((lg >> 1) * 16);                  // + kstep*32
    const uint32_t b_row = (uint32_t)(nwarp * 64 + (lg >> 1) * 8 + li);  // + npair*16
    const uint32_t b_colh = (uint32_t)((lg & 1) * 16);                   // + kstep*32

    int accH[2][8][4], accL[2][8][4];
#pragma unroll
    for (int i = 0; i < 2; i++)
#pragma unroll
        for (int j = 0; j < 8; j++)
#pragma unroll
            for (int c = 0; c < 4; c++) { accH[i][j][c] = 0; accL[i][j][c] = 0; }

#pragma unroll 1
    for (int g = 0; g < NKS; ++g) {
        int s = g & (STAGES - 1);
        int r = g >> 2;
        MBAR_WAIT(sb + 8 * s, r & 1);

        uint32_t sAH = data + s * STAGE_BYTES;
        uint32_t sAL = sAH + TILE_BYTES;
        uint32_t sBB = sAH + 2 * TILE_BYTES;

#pragma unroll
        for (int kstep = 0; kstep < 4; ++kstep) {
            uint32_t acol = ((uint32_t)(kstep * 32) + a_colh) ^ xorc;
            uint32_t bcol = ((uint32_t)(kstep * 32) + b_colh) ^ xorc;
            uint32_t aH[2][4], aL[2][4], bm[4][4];
#pragma unroll
            for (int mt = 0; mt < 2; ++mt) {
                uint32_t ra = (a_row + mt * 16) * 128 + acol;
                LDSM_X4(aH[mt][0], aH[mt][1], aH[mt][2], aH[mt][3], sAH + ra);
                LDSM_X4(aL[mt][0], aL[mt][1], aL[mt][2], aL[mt][3], sAL + ra);
            }
#pragma unroll
            for (int np = 0; np < 4; ++np) {
                uint32_t rb = (b_row + np * 16) * 128 + bcol;
                LDSM_X4(bm[np][0], bm[np][1], bm[np][2], bm[np][3], sBB + rb);
            }
#pragma unroll
            for (int mt = 0; mt < 2; ++mt)
#pragma unroll
                for (int nj = 0; nj < 8; ++nj) {
                    uint32_t b0 = bm[nj >> 1][(nj & 1) * 2];
                    uint32_t b1 = bm[nj >> 1][(nj & 1) * 2 + 1];
                    IMMA16832(accH[mt][nj], aH[mt], b0, b1);
                    IMMA16832(accL[mt][nj], aL[mt], b0, b1);
                }
        }

        if (lid == 0) MBAR_ARRIVE(sb + 64 + 8 * s);

        if (tid == 0 && g + STAGES < NKS) {
            MBAR_WAIT(sb + 64 + 8 * s, r & 1);
            int ks = g + STAGES;
            size_t tb = (size_t)(mtb * NKS + ks) * TILE_BYTES;
            size_t bb = (size_t)(nt * NKS + ks) * TILE_BYTES;
            MBAR_EXPECT_TX(sb + 8 * s, STAGE_BYTES);
            BULK_G2S(sAH, g_AH + tb, TILE_BYTES, sb + 8 * s);
            BULK_G2S(sAL, g_AL + tb, TILE_BYTES, sb + 8 * s);
            BULK_G2S(sBB, g_B  + bb, TILE_BYTES, sb + 8 * s);
        }
    }

    // ---- epilogue: out = scale*a*(256*accH + accL - zp*irs) + bias ----
    const int t4 = lid >> 2;
    const int c2 = (lid & 3) * 2;
#pragma unroll
    for (int mt = 0; mt < 2; ++mt) {
        int r0 = mtb * 128 + mwarp * 32 + mt * 16 + t4;
        float a0 = g_a[r0],       a1 = g_a[r0 + 8];
        float fi0 = (float)g_irs[r0], fi1 = (float)g_irs[r0 + 8];
        float* row0 = out + (size_t)r0 * DK;
        float* row1 = row0 + (size_t)8 * DK;
#pragma unroll
        for (int nj = 0; nj < 8; ++nj) {
            int n = nt * 128 + nwarp * 64 + nj * 8 + c2;
            float sc0 = __ldg(scale + n),     sc1 = __ldg(scale + n + 1);
            float bi0 = __ldg(bias + n),      bi1 = __ldg(bias + n + 1);
            float z0  = (float)__ldg(zp + n), z1  = (float)__ldg(zp + n + 1);
            float v00 = 256.0f * (float)accH[mt][nj][0] + (float)accL[mt][nj][0];
            float v01 = 256.0f * (float)accH[mt][nj][1] + (float)accL[mt][nj][1];
            float v10 = 256.0f * (float)accH[mt][nj][2] + (float)accL[mt][nj][2];
            float v11 = 256.0f * (float)accH[mt][nj][3] + (float)accL[mt][nj][3];
            float2 o0, o1;
            o0.x = sc0 * a0 * (v00 - z0 * fi0) + bi0;
            o0.y = sc1 * a0 * (v01 - z1 * fi0) + bi1;
            o1.x = sc0 * a1 * (v10 - z0 * fi1) + bi0;
            o1.y = sc1 * a1 * (v11 - z1 * fi1) + bi1;
            *reinterpret_cast<float2*>(row0 + n) = o0;
            *reinterpret_cast<float2*>(row1 + n) = o1;
        }
    }
}

// ---------------- launch ----------------
extern "C" void kernel_launch(void* const* d_in, const int* in_sizes, int n_in,
                              void* d_out, int out_size) {
    const float* x     = (const float*)d_in[0];
    const int*   q     = (const int*)  d_in[1];
    const float* scale = (const float*)d_in[2];
    const int*   zp    = (const int*)  d_in[3];
    const float* bias  = (const float*)d_in[4];
    float* out = (float*)d_out;

    cudaFuncSetAttribute(ffq_gemm_kernel,
                         cudaFuncAttributeMaxDynamicSharedMemorySize, SMEM_BYTES);

    rowmax_kernel<<<MTOT, 256>>>(x);             // 4096 blocks
    pack_x_kernel<<<NMT * NKS, 256>>>(x);        // 1024 blocks
    pack_q_kernel<<<NNT * NKS, 256>>>(q);        // 1024 blocks
    ffq_gemm_kernel<<<dim3(NNT, NMT), 256, SMEM_BYTES>>>(scale, zp, bias, out);
}

// round 4
// speedup vs baseline: 5.7647x; 5.7647x over previous
#include <cuda_runtime.h>
#include <cuda_fp16.h>
#include <cstdint>
#include <cstddef>

// ---------------- problem constants ----------------
static constexpr int DK   = 4096;          // inner dim == output dim
static constexpr int MTOT = 4096;          // B*S
static constexpr int TM = 128, TN = 128, TK = 64;
static constexpr int NMT = MTOT / TM;      // 32
static constexpr int NNT = DK / TN;        // 32
static constexpr int NKS = DK / TK;        // 64 k-stages, single pass
static constexpr int STAGES = 6;
static constexpr int A_STAGE = TM * TK * 2;              // 16384
static constexpr int B_STAGE = TK * TN * 2;              // 16384
static constexpr int STAGE_BYTES = A_STAGE + B_STAGE;    // 32768
static constexpr int SMEM_BYTES  = 1024 + STAGES * STAGE_BYTES; // 197632

// ---------------- scratch (pre-packed, pre-swizzled fp16 tiles) -------------
__device__ __align__(1024) __half g_A[(size_t)NMT * NKS * TM * TK]; // 32MB
__device__ __align__(1024) __half g_B[(size_t)NNT * NKS * TK * TN]; // 32MB
__device__ float g_rowsum[MTOT];

// ---------------- helpers ----------------
__device__ __forceinline__ uint32_t smem_u32(const void* p) {
    uint32_t a;
    asm("{ .reg .u64 t; cvta.to.shared.u64 t, %1; cvt.u32.u64 %0, t; }"
        : "=r"(a) : "l"(p));
    return a;
}
// A tiles: 128B rows -> XOR bits[6:4] with bits[9:7]
__device__ __forceinline__ uint32_t swzA(uint32_t off) {
    return off ^ ((off >> 3) & 0x70);
}
// B tiles: 256B rows -> XOR bits[6:4] with bits[10:8]
__device__ __forceinline__ uint32_t swzB(uint32_t off) {
    return off ^ ((off >> 4) & 0x70);
}

#define MBAR_INIT(mbar, cnt) \
    asm volatile("mbarrier.init.shared.b64 [%0], %1;" :: "r"(mbar), "r"(cnt) : "memory")
#define MBAR_ARRIVE(mbar) \
    asm volatile("mbarrier.arrive.shared.b64 _, [%0];" :: "r"(mbar) : "memory")
#define MBAR_EXPECT_TX(mbar, bytes) \
    asm volatile("mbarrier.arrive.expect_tx.shared.b64 _, [%0], %1;" \
                 :: "r"(mbar), "r"(bytes) : "memory")
#define MBAR_WAIT(mbar, parity) do {                                          \
    asm volatile(                                                             \
        "{\n\t.reg .pred P1;\n\t"                                             \
        "W_%=:\n\t"                                                           \
        "mbarrier.try_wait.parity.acquire.cta.shared::cta.b64 P1, [%0], %1, 0x989680;\n\t" \
        "@P1 bra.uni D_%=;\n\t"                                               \
        "bra.uni W_%=;\n\t"                                                   \
        "D_%=:\n\t}"                                                          \
        :: "r"((uint32_t)(mbar)), "r"((uint32_t)(parity)) : "memory");        \
} while (0)
#define BULK_G2S(dst, src, bytes, mbar)                                       \
    asm volatile(                                                             \
        "cp.async.bulk.shared::cluster.global.mbarrier::complete_tx::bytes "  \
        "[%0], [%1], %2, [%3];"                                               \
        :: "r"((uint32_t)(dst)), "l"(src), "r"((uint32_t)(bytes)),            \
           "r"((uint32_t)(mbar)) : "memory")

#define LDSM_X4(r0, r1, r2, r3, addr)                                         \
    asm volatile("ldmatrix.sync.aligned.m8n8.x4.shared.b16 {%0,%1,%2,%3}, [%4];" \
        : "=r"(r0), "=r"(r1), "=r"(r2), "=r"(r3) : "r"(addr))
#define LDSM_X4_T(r0, r1, r2, r3, addr)                                       \
    asm volatile("ldmatrix.sync.aligned.m8n8.x4.trans.shared.b16 {%0,%1,%2,%3}, [%4];" \
        : "=r"(r0), "=r"(r1), "=r"(r2), "=r"(r3) : "r"(addr))

#define MMA16816F16(d, a, b0, b1)                                             \
    asm volatile(                                                             \
        "mma.sync.aligned.m16n8k16.row.col.f32.f16.f16.f32 "                  \
        "{%0,%1,%2,%3}, {%4,%5,%6,%7}, {%8,%9}, {%0,%1,%2,%3};"               \
        : "+f"((d)[0]), "+f"((d)[1]), "+f"((d)[2]), "+f"((d)[3])              \
        : "r"((a)[0]), "r"((a)[1]), "r"((a)[2]), "r"((a)[3]),                 \
          "r"(b0), "r"(b1))

// ---------------- pack kernels ----------------
// A: x[4096,4096] fp32 -> fp16 tiles [mt][ks][128 rows x 128B, swzA]
__global__ void __launch_bounds__(256) pack_x_kernel(const float* __restrict__ x) {
    int b = blockIdx.x;                 // mt*64 + ks
    int mt = b >> 6, ks = b & 63;
    size_t base = (size_t)b * A_STAGE;
#pragma unroll
    for (int p = 0; p < 4; p++) {
        int idx = threadIdx.x + p * 256;            // [0,1024)
        int ml = idx >> 3, k8 = idx & 7;
        size_t gm = (size_t)(mt * 128 + ml) * DK + ks * 64 + k8 * 8;
        float4 f0 = *reinterpret_cast<const float4*>(x + gm);
        float4 f1 = *reinterpret_cast<const float4*>(x + gm + 4);
        float v[8] = {f0.x, f0.y, f0.z, f0.w, f1.x, f1.y, f1.z, f1.w};
        uint32_t w[4];
#pragma unroll
        for (int i = 0; i < 4; i++) {
            __half h0 = __float2half_rn(v[2 * i]);
            __half h1 = __float2half_rn(v[2 * i + 1]);
            w[i] = (uint32_t)__half_as_ushort(h0) |
                   ((uint32_t)__half_as_ushort(h1) << 16);
        }
        uint32_t off = swzA((uint32_t)(ml * 128 + k8 * 16));
        *reinterpret_cast<uint4*>((char*)g_A + base + off) =
            make_uint4(w[0], w[1], w[2], w[3]);
    }
}

// B: q[k][n] int32 (0..255, exact in fp16) -> tiles [nt][ks][64 k x 256B, swzB]
__global__ void __launch_bounds__(256) pack_q_kernel(const int* __restrict__ q) {
    int b = blockIdx.x;                 // nt*64 + ks
    int nt = b >> 6, ks = b & 63;
    size_t base = (size_t)b * B_STAGE;
#pragma unroll
    for (int p = 0; p < 4; p++) {
        int idx = threadIdx.x + p * 256;            // [0,1024)
        int kl = idx >> 4, c8 = idx & 15;           // 64 rows x 16 chunks of 8n
        const int* src = q + (size_t)(ks * 64 + kl) * DK + nt * 128 + c8 * 8;
        int4 q0 = *reinterpret_cast<const int4*>(src);
        int4 q1 = *reinterpret_cast<const int4*>(src + 4);
        int vi[8] = {q0.x, q0.y, q0.z, q0.w, q1.x, q1.y, q1.z, q1.w};
        uint32_t w[4];
#pragma unroll
        for (int i = 0; i < 4; i++) {
            __half b0 = __float2half_rn((float)vi[2 * i]);
            __half b1 = __float2half_rn((float)vi[2 * i + 1]);
            w[i] = (uint32_t)__half_as_ushort(b0) |
                   ((uint32_t)__half_as_ushort(b1) << 16);
        }
        uint32_t off = swzB((uint32_t)(kl * 256 + c8 * 16));
        *reinterpret_cast<uint4*>((char*)g_B + base + off) =
            make_uint4(w[0], w[1], w[2], w[3]);
    }
}

// deterministic per-row sum of x (for the zero_point term)
__global__ void __launch_bounds__(256) rowsum_kernel(const float* __restrict__ x) {
    __shared__ float red[256];
    int r = blockIdx.x, t = threadIdx.x;
    float s = 0.0f;
#pragma unroll
    for (int j = 0; j < 16; j++) s += x[(size_t)r * DK + t + j * 256];
    red[t] = s;
    __syncthreads();
#pragma unroll
    for (int o = 128; o > 0; o >>= 1) {
        if (t < o) red[t] += red[t + o];
        __syncthreads();
    }
    if (t == 0) g_rowsum[r] = red[0];
}

// ---------------- main GEMM: fp16 mma.sync, 6-stage bulk-copy pipeline ------
__global__ void __launch_bounds__(256, 1)
ffq_gemm_kernel(const float* __restrict__ scale, const int* __restrict__ zp,
                const float* __restrict__ bias, float* __restrict__ out) {
    extern __shared__ char smem_raw[];
    uint32_t sb = (smem_u32(smem_raw) + 1023u) & ~1023u;   // ctrl base
    const uint32_t data = sb + 1024;                       // stage s at data + s*32768

    const int tid = threadIdx.x;
    const int wid = tid >> 5, lid = tid & 31;
    const int nt = blockIdx.x, mtb = blockIdx.y;
    const int mwarp = wid & 3;            // 4 M-rows of 32
    const int nwarp = wid >> 2;           // 2 N-cols of 64

    // full[s] @ sb+8s (tx-based), empty[s] @ sb+64+8s (8 warp arrivals)
    if (tid == 0) {
#pragma unroll
        for (int s = 0; s < STAGES; s++) {
            MBAR_INIT(sb + 8 * s, 1);
            MBAR_INIT(sb + 64 + 8 * s, 8);
        }
        asm volatile("fence.proxy.async.shared::cta;" ::: "memory");
    }
    __syncthreads();

    // prologue: fill stages 0..5 with ks = s
    if (tid == 0) {
#pragma unroll
        for (int s = 0; s < STAGES; s++) {
            const char* srcA = (const char*)g_A + (size_t)(mtb * NKS + s) * A_STAGE;
            const char* srcB = (const char*)g_B + (size_t)(nt  * NKS + s) * B_STAGE;
            uint32_t st = data + s * STAGE_BYTES;
            MBAR_EXPECT_TX(sb + 8 * s, STAGE_BYTES);
            BULK_G2S(st,           srcA, A_STAGE, sb + 8 * s);
            BULK_G2S(st + A_STAGE, srcB, B_STAGE, sb + 8 * s);
        }
    }

    // per-lane ldmatrix address components
    const int lg = lid >> 3, li = lid & 7;
    const uint32_t xorc  = (uint32_t)li << 4;
    const uint32_t a_row = (uint32_t)(mwarp * 32 + (lg & 1) * 8 + li);
    const uint32_t acolh = (uint32_t)((lg >> 1) * 16);
    const uint32_t b_klo = (uint32_t)((lg & 1) * 8 + li);
    const uint32_t bcolh = (uint32_t)(nwarp * 128 + (lg >> 1) * 16);

    float acc[2][8][4];
#pragma unroll
    for (int i = 0; i < 2; i++)
#pragma unroll
        for (int j = 0; j < 8; j++)
#pragma unroll
            for (int c = 0; c < 4; c++) acc[i][j][c] = 0.0f;

    int s = 0, ph = 0;
#pragma unroll 1
    for (int g = 0; g < NKS; ++g) {
        MBAR_WAIT(sb + 8 * s, ph);

        uint32_t sA = data + s * STAGE_BYTES;
        uint32_t sB = sA + A_STAGE;
        uint32_t a[2][4], bm[4][4];
#pragma unroll
        for (int k16 = 0; k16 < 4; ++k16) {
#pragma unroll
            for (int mt = 0; mt < 2; ++mt) {
                uint32_t addr = sA + (a_row + mt * 16) * 128 +
                                (((uint32_t)(k16 * 32) + acolh) ^ xorc);
                LDSM_X4(a[mt][0], a[mt][1], a[mt][2], a[mt][3], addr);
            }
#pragma unroll
            for (int ng = 0; ng < 4; ++ng) {
                uint32_t addr = sB + (b_klo + k16 * 16) * 256 +
                                (((uint32_t)(ng * 32) + bcolh) ^ xorc);
                LDSM_X4_T(bm[ng][0], bm[ng][1], bm[ng][2], bm[ng][3], addr);
            }
#pragma unroll
            for (int mt = 0; mt < 2; ++mt)
#pragma unroll
                for (int nj = 0; nj < 8; ++nj)
                    MMA16816F16(acc[mt][nj], a[mt],
                                bm[nj >> 1][(nj & 1) * 2],
                                bm[nj >> 1][(nj & 1) * 2 + 1]);
        }

        if (lid == 0) MBAR_ARRIVE(sb + 64 + 8 * s);

        if (tid == 0 && g + STAGES < NKS) {
            MBAR_WAIT(sb + 64 + 8 * s, ph);      // all 8 warps done with stage
            int ks = g + STAGES;
            const char* srcA = (const char*)g_A + (size_t)(mtb * NKS + ks) * A_STAGE;
            const char* srcB = (const char*)g_B + (size_t)(nt  * NKS + ks) * B_STAGE;
            MBAR_EXPECT_TX(sb + 8 * s, STAGE_BYTES);
            BULK_G2S(sA, srcA, A_STAGE, sb + 8 * s);
            BULK_G2S(sB, srcB, B_STAGE, sb + 8 * s);
        }

        if (++s == STAGES) { s = 0; ph ^= 1; }
    }

    // ---- epilogue: out = acc*scale - rowsum*zp*scale + bias ----
    const int t4 = lid >> 2;
    const int c2 = (lid & 3) * 2;
#pragma unroll
    for (int mt = 0; mt < 2; ++mt) {
        int m0 = mtb * 128 + mwarp * 32 + mt * 16 + t4;
        float rs0 = g_rowsum[m0];
        float rs1 = g_rowsum[m0 + 8];
        float* row0 = out + (size_t)m0 * DK;
        float* row1 = row0 + (size_t)8 * DK;
#pragma unroll
        for (int nj = 0; nj < 8; ++nj) {
            int n = nt * 128 + nwarp * 64 + nj * 8 + c2;
            float sc0 = __ldg(scale + n),     sc1 = __ldg(scale + n + 1);
            float bi0 = __ldg(bias + n),      bi1 = __ldg(bias + n + 1);
            float zs0 = (float)__ldg(zp + n)     * sc0;
            float zs1 = (float)__ldg(zp + n + 1) * sc1;
            float2 o0, o1;
            o0.x = acc[mt][nj][0] * sc0 + bi0 - rs0 * zs0;
            o0.y = acc[mt][nj][1] * sc1 + bi1 - rs0 * zs1;
            o1.x = acc[mt][nj][2] * sc0 + bi0 - rs1 * zs0;
            o1.y = acc[mt][nj][3] * sc1 + bi1 - rs1 * zs1;
            *reinterpret_cast<float2*>(row0 + n) = o0;
            *reinterpret_cast<float2*>(row1 + n) = o1;
        }
    }
}

// ---------------- launch ----------------
extern "C" void kernel_launch(void* const* d_in, const int* in_sizes, int n_in,
                              void* d_out, int out_size) {
    const float* x     = (const float*)d_in[0];
    const int*   q     = (const int*)  d_in[1];
    const float* scale = (const float*)d_in[2];
    const int*   zp    = (const int*)  d_in[3];
    const float* bias  = (const float*)d_in[4];
    float* out = (float*)d_out;

    cudaFuncSetAttribute(ffq_gemm_kernel,
                         cudaFuncAttributeMaxDynamicSharedMemorySize, SMEM_BYTES);

    pack_x_kernel<<<NMT * NKS, 256>>>(x);        // 2048 blocks
    pack_q_kernel<<<NNT * NKS, 256>>>(q);        // 2048 blocks
    rowsum_kernel<<<MTOT, 256>>>(x);             // 4096 blocks
    ffq_gemm_kernel<<<dim3(NNT, NMT), 256, SMEM_BYTES>>>(scale, zp, bias, out);
}

// round 5
// speedup vs baseline: 5.8556x; 1.0158x over previous
#include <cuda_runtime.h>
#include <cuda_fp16.h>
#include <cstdint>
#include <cstddef>

// ---------------- problem constants ----------------
static constexpr int DK   = 4096;          // inner dim == output dim
static constexpr int MTOT = 4096;          // B*S
static constexpr int TM = 128, TN = 128, TK = 64;
static constexpr int NMT = MTOT / TM;      // 32
static constexpr int NNT = DK / TN;        // 32
static constexpr int NKS = DK / TK;        // 64 k-stages, single pass
static constexpr int STAGES = 3;
static constexpr int A_STAGE = TM * TK * 2;              // 16384
static constexpr int B_STAGE = TK * TN * 2;              // 16384
static constexpr int STAGE_BYTES = A_STAGE + B_STAGE;    // 32768
static constexpr int SMEM_BYTES  = 1024 + STAGES * STAGE_BYTES; // 99328 -> 2 CTAs/SM

// ---------------- scratch (pre-packed, pre-swizzled fp16 tiles) -------------
__device__ __align__(1024) __half g_A[(size_t)NMT * NKS * TM * TK]; // 32MB
__device__ __align__(1024) __half g_B[(size_t)NNT * NKS * TK * TN]; // 32MB
__device__ float g_rowsum[MTOT];

// ---------------- helpers ----------------
__device__ __forceinline__ uint32_t smem_u32(const void* p) {
    uint32_t a;
    asm("{ .reg .u64 t; cvta.to.shared.u64 t, %1; cvt.u32.u64 %0, t; }"
        : "=r"(a) : "l"(p));
    return a;
}
// A tiles: 128B rows -> XOR bits[6:4] with bits[9:7]
__device__ __forceinline__ uint32_t swzA(uint32_t off) {
    return off ^ ((off >> 3) & 0x70);
}
// B tiles: 256B rows -> XOR bits[6:4] with bits[10:8]
__device__ __forceinline__ uint32_t swzB(uint32_t off) {
    return off ^ ((off >> 4) & 0x70);
}

#define MBAR_INIT(mbar, cnt) \
    asm volatile("mbarrier.init.shared.b64 [%0], %1;" :: "r"(mbar), "r"(cnt) : "memory")
#define MBAR_ARRIVE(mbar) \
    asm volatile("mbarrier.arrive.shared.b64 _, [%0];" :: "r"(mbar) : "memory")
#define MBAR_EXPECT_TX(mbar, bytes) \
    asm volatile("mbarrier.arrive.expect_tx.shared.b64 _, [%0], %1;" \
                 :: "r"(mbar), "r"(bytes) : "memory")
#define MBAR_WAIT(mbar, parity) do {                                          \
    asm volatile(                                                             \
        "{\n\t.reg .pred P1;\n\t"                                             \
        "W_%=:\n\t"                                                           \
        "mbarrier.try_wait.parity.acquire.cta.shared::cta.b64 P1, [%0], %1, 0x989680;\n\t" \
        "@P1 bra.uni D_%=;\n\t"                                               \
        "bra.uni W_%=;\n\t"                                                   \
        "D_%=:\n\t}"                                                          \
        :: "r"((uint32_t)(mbar)), "r"((uint32_t)(parity)) : "memory");        \
} while (0)
#define BULK_G2S(dst, src, bytes, mbar)                                       \
    asm volatile(                                                             \
        "cp.async.bulk.shared::cluster.global.mbarrier::complete_tx::bytes "  \
        "[%0], [%1], %2, [%3];"                                               \
        :: "r"((uint32_t)(dst)), "l"(src), "r"((uint32_t)(bytes)),            \
           "r"((uint32_t)(mbar)) : "memory")

#define LDSM_X4(r0, r1, r2, r3, addr)                                         \
    asm volatile("ldmatrix.sync.aligned.m8n8.x4.shared.b16 {%0,%1,%2,%3}, [%4];" \
        : "=r"(r0), "=r"(r1), "=r"(r2), "=r"(r3) : "r"(addr))
#define LDSM_X4_T(r0, r1, r2, r3, addr)                                       \
    asm volatile("ldmatrix.sync.aligned.m8n8.x4.trans.shared.b16 {%0,%1,%2,%3}, [%4];" \
        : "=r"(r0), "=r"(r1), "=r"(r2), "=r"(r3) : "r"(addr))

#define MMA16816F16(d, a, b0, b1)                                             \
    asm volatile(                                                             \
        "mma.sync.aligned.m16n8k16.row.col.f32.f16.f16.f32 "                  \
        "{%0,%1,%2,%3}, {%4,%5,%6,%7}, {%8,%9}, {%0,%1,%2,%3};"               \
        : "+f"((d)[0]), "+f"((d)[1]), "+f"((d)[2]), "+f"((d)[3])              \
        : "r"((a)[0]), "r"((a)[1]), "r"((a)[2]), "r"((a)[3]),                 \
          "r"(b0), "r"(b1))

// ---------------- pack kernels ----------------
// A: x[4096,4096] fp32 -> fp16 tiles [mt][ks][128 rows x 128B, swzA]
__global__ void __launch_bounds__(256) pack_x_kernel(const float* __restrict__ x) {
    int b = blockIdx.x;                 // mt*64 + ks
    int mt = b >> 6, ks = b & 63;
    size_t base = (size_t)b * A_STAGE;
#pragma unroll
    for (int p = 0; p < 4; p++) {
        int idx = threadIdx.x + p * 256;            // [0,1024)
        int ml = idx >> 3, k8 = idx & 7;
        size_t gm = (size_t)(mt * 128 + ml) * DK + ks * 64 + k8 * 8;
        float4 f0 = *reinterpret_cast<const float4*>(x + gm);
        float4 f1 = *reinterpret_cast<const float4*>(x + gm + 4);
        float v[8] = {f0.x, f0.y, f0.z, f0.w, f1.x, f1.y, f1.z, f1.w};
        uint32_t w[4];
#pragma unroll
        for (int i = 0; i < 4; i++) {
            __half h0 = __float2half_rn(v[2 * i]);
            __half h1 = __float2half_rn(v[2 * i + 1]);
            w[i] = (uint32_t)__half_as_ushort(h0) |
                   ((uint32_t)__half_as_ushort(h1) << 16);
        }
        uint32_t off = swzA((uint32_t)(ml * 128 + k8 * 16));
        *reinterpret_cast<uint4*>((char*)g_A + base + off) =
            make_uint4(w[0], w[1], w[2], w[3]);
    }
}

// B: q[k][n] int32 (0..255, exact in fp16) -> tiles [nt][ks][64 k x 256B, swzB]
__global__ void __launch_bounds__(256) pack_q_kernel(const int* __restrict__ q) {
    int b = blockIdx.x;                 // nt*64 + ks
    int nt = b >> 6, ks = b & 63;
    size_t base = (size_t)b * B_STAGE;
#pragma unroll
    for (int p = 0; p < 4; p++) {
        int idx = threadIdx.x + p * 256;            // [0,1024)
        int kl = idx >> 4, c8 = idx & 15;           // 64 rows x 16 chunks of 8n
        const int* src = q + (size_t)(ks * 64 + kl) * DK + nt * 128 + c8 * 8;
        int4 q0 = *reinterpret_cast<const int4*>(src);
        int4 q1 = *reinterpret_cast<const int4*>(src + 4);
        int vi[8] = {q0.x, q0.y, q0.z, q0.w, q1.x, q1.y, q1.z, q1.w};
        uint32_t w[4];
#pragma unroll
        for (int i = 0; i < 4; i++) {
            __half b0 = __float2half_rn((float)vi[2 * i]);
            __half b1 = __float2half_rn((float)vi[2 * i + 1]);
            w[i] = (uint32_t)__half_as_ushort(b0) |
                   ((uint32_t)__half_as_ushort(b1) << 16);
        }
        uint32_t off = swzB((uint32_t)(kl * 256 + c8 * 16));
        *reinterpret_cast<uint4*>((char*)g_B + base + off) =
            make_uint4(w[0], w[1], w[2], w[3]);
    }
}

// deterministic per-row sum of x (for the zero_point term)
__global__ void __launch_bounds__(256) rowsum_kernel(const float* __restrict__ x) {
    __shared__ float red[256];
    int r = blockIdx.x, t = threadIdx.x;
    float s = 0.0f;
#pragma unroll
    for (int j = 0; j < 16; j++) s += x[(size_t)r * DK + t + j * 256];
    red[t] = s;
    __syncthreads();
#pragma unroll
    for (int o = 128; o > 0; o >>= 1) {
        if (t < o) red[t] += red[t + o];
        __syncthreads();
    }
    if (t == 0) g_rowsum[r] = red[0];
}

// ---------------- main GEMM: fp16 mma.sync, 3-stage pipeline, 2 CTA/SM ------
__global__ void __launch_bounds__(256, 2)
ffq_gemm_kernel(const float* __restrict__ scale, const int* __restrict__ zp,
                const float* __restrict__ bias, float* __restrict__ out) {
    extern __shared__ char smem_raw[];
    uint32_t sb = (smem_u32(smem_raw) + 1023u) & ~1023u;   // ctrl base
    const uint32_t data = sb + 1024;                       // stage s at data + s*32768

    const int tid = threadIdx.x;
    const int wid = tid >> 5, lid = tid & 31;
    const int nt = blockIdx.x, mtb = blockIdx.y;
    const int mwarp = wid & 3;            // 4 M-rows of 32
    const int nwarp = wid >> 2;           // 2 N-cols of 64

    // full[s] @ sb+8s (tx-based), empty[s] @ sb+64+8s (8 warp arrivals)
    if (tid == 0) {
#pragma unroll
        for (int s = 0; s < STAGES; s++) {
            MBAR_INIT(sb + 8 * s, 1);
            MBAR_INIT(sb + 64 + 8 * s, 8);
        }
        asm volatile("fence.proxy.async.shared::cta;" ::: "memory");
    }
    __syncthreads();

    // prologue: fill stages 0..2 with ks = s
    if (tid == 0) {
#pragma unroll
        for (int s = 0; s < STAGES; s++) {
            const char* srcA = (const char*)g_A + (size_t)(mtb * NKS + s) * A_STAGE;
            const char* srcB = (const char*)g_B + (size_t)(nt  * NKS + s) * B_STAGE;
            uint32_t st = data + s * STAGE_BYTES;
            MBAR_EXPECT_TX(sb + 8 * s, STAGE_BYTES);
            BULK_G2S(st,           srcA, A_STAGE, sb + 8 * s);
            BULK_G2S(st + A_STAGE, srcB, B_STAGE, sb + 8 * s);
        }
    }

    // per-lane ldmatrix address components
    const int lg = lid >> 3, li = lid & 7;
    const uint32_t xorc  = (uint32_t)li << 4;
    const uint32_t a_row = (uint32_t)(mwarp * 32 + (lg & 1) * 8 + li);
    const uint32_t acolh = (uint32_t)((lg >> 1) * 16);
    const uint32_t b_klo = (uint32_t)((lg & 1) * 8 + li);
    const uint32_t bcolh = (uint32_t)(nwarp * 128 + (lg >> 1) * 16);

    float acc[2][8][4];
#pragma unroll
    for (int i = 0; i < 2; i++)
#pragma unroll
        for (int j = 0; j < 8; j++)
#pragma unroll
            for (int c = 0; c < 4; c++) acc[i][j][c] = 0.0f;

    int s = 0, ph = 0;
#pragma unroll 1
    for (int g = 0; g < NKS; ++g) {
        MBAR_WAIT(sb + 8 * s, ph);

        uint32_t sA = data + s * STAGE_BYTES;
        uint32_t sB = sA + A_STAGE;
#pragma unroll
        for (int k16 = 0; k16 < 4; ++k16) {
            // low register pressure: stage A once, stream B one x4 at a time
            uint32_t a0[4], a1[4];
            uint32_t ra = a_row * 128 + (((uint32_t)(k16 * 32) + acolh) ^ xorc);
            LDSM_X4(a0[0], a0[1], a0[2], a0[3], sA + ra);
            LDSM_X4(a1[0], a1[1], a1[2], a1[3], sA + ra + 16 * 128);
#pragma unroll
            for (int ng = 0; ng < 4; ++ng) {
                uint32_t b0, b1, b2, b3;
                uint32_t rb = sB + (b_klo + k16 * 16) * 256 +
                              (((uint32_t)(ng * 32) + bcolh) ^ xorc);
                LDSM_X4_T(b0, b1, b2, b3, rb);
                MMA16816F16(acc[0][2 * ng],     a0, b0, b1);
                MMA16816F16(acc[0][2 * ng + 1], a0, b2, b3);
                MMA16816F16(acc[1][2 * ng],     a1, b0, b1);
                MMA16816F16(acc[1][2 * ng + 1], a1, b2, b3);
            }
        }

        if (lid == 0) MBAR_ARRIVE(sb + 64 + 8 * s);

        if (tid == 0 && g + STAGES < NKS) {
            MBAR_WAIT(sb + 64 + 8 * s, ph);      // all 8 warps done with stage
            int ks = g + STAGES;
            const char* srcA = (const char*)g_A + (size_t)(mtb * NKS + ks) * A_STAGE;
            const char* srcB = (const char*)g_B + (size_t)(nt  * NKS + ks) * B_STAGE;
            MBAR_EXPECT_TX(sb + 8 * s, STAGE_BYTES);
            BULK_G2S(sA, srcA, A_STAGE, sb + 8 * s);
            BULK_G2S(sB, srcB, B_STAGE, sb + 8 * s);
        }

        if (++s == STAGES) { s = 0; ph ^= 1; }
    }

    // ---- epilogue: out = acc*scale - rowsum*zp*scale + bias ----
    const int t4 = lid >> 2;
    const int c2 = (lid & 3) * 2;
#pragma unroll
    for (int mt = 0; mt < 2; ++mt) {
        int m0 = mtb * 128 + mwarp * 32 + mt * 16 + t4;
        float rs0 = g_rowsum[m0];
        float rs1 = g_rowsum[m0 + 8];
        float* row0 = out + (size_t)m0 * DK;
        float* row1 = row0 + (size_t)8 * DK;
#pragma unroll
        for (int nj = 0; nj < 8; ++nj) {
            int n = nt * 128 + nwarp * 64 + nj * 8 + c2;
            float sc0 = __ldg(scale + n),     sc1 = __ldg(scale + n + 1);
            float bi0 = __ldg(bias + n),      bi1 = __ldg(bias + n + 1);
            float zs0 = (float)__ldg(zp + n)     * sc0;
            float zs1 = (float)__ldg(zp + n + 1) * sc1;
            float2 o0, o1;
            o0.x = acc[mt][nj][0] * sc0 + bi0 - rs0 * zs0;
            o0.y = acc[mt][nj][1] * sc1 + bi1 - rs0 * zs1;
            o1.x = acc[mt][nj][2] * sc0 + bi0 - rs1 * zs0;
            o1.y = acc[mt][nj][3] * sc1 + bi1 - rs1 * zs1;
            *reinterpret_cast<float2*>(row0 + n) = o0;
            *reinterpret_cast<float2*>(row1 + n) = o1;
        }
    }
}

// ---------------- launch ----------------
extern "C" void kernel_launch(void* const* d_in, const int* in_sizes, int n_in,
                              void* d_out, int out_size) {
    const float* x     = (const float*)d_in[0];
    const int*   q     = (const int*)  d_in[1];
    const float* scale = (const float*)d_in[2];
    const int*   zp    = (const int*)  d_in[3];
    const float* bias  = (const float*)d_in[4];
    float* out = (float*)d_out;

    cudaFuncSetAttribute(ffq_gemm_kernel,
                         cudaFuncAttributeMaxDynamicSharedMemorySize, SMEM_BYTES);

    pack_x_kernel<<<NMT * NKS, 256>>>(x);        // 2048 blocks
    pack_q_kernel<<<NNT * NKS, 256>>>(q);        // 2048 blocks
    rowsum_kernel<<<MTOT, 256>>>(x);             // 4096 blocks
    ffq_gemm_kernel<<<dim3(NNT, NMT), 256, SMEM_BYTES>>>(scale, zp, bias, out);
}